// round 11
// baseline (speedup 1.0000x reference)
#include <cuda_runtime.h>
#include <cuda_fp16.h>
#include <stdint.h>
#include <math.h>

#define NB   2048
#define NT   64
#define NL   8
#define NH   64
#define NSEQ (NB*NL)          // 16384
#define RPC  64               // rows per GRU CTA
#define GCTA (NSEQ/RPC)       // 256 CTAs
#define GT   256              // GRU threads per CTA

// ---- SMEM map for GRU mainloop (bytes) -------------------------------------
#define SO_B2   0
#define SO_B4   16384
#define SO_BK2  32768
#define SO_BK4  36864
#define SO_A    45056
#define SMEMSZ  65536

// ---- scratch (__device__ globals; allocs forbidden) -----------------------
__device__ __align__(16) float g_hidden[NSEQ * NH];   // [seq][64]
__device__ __align__(16) char g_Ball[45056];          // packed B regions
__device__ __align__(16) float g_yc[NL * 7 * 20];     // relu(ce@Wcc^T+bcc)

__device__ __forceinline__ float sigf(float x) {
    return __fdividef(1.0f, 1.0f + __expf(-x));
}
__device__ __forceinline__ float tanha(float x) {
    float y;
    asm("tanh.approx.f32 %0, %1;" : "=f"(y) : "f"(x));
    return y;
}
__device__ __forceinline__ float siga(float x) {     // sigmoid via tanh, 1 MUFU
    return fmaf(0.5f, tanha(0.5f * x), 0.5f);
}
__device__ __forceinline__ uint32_t h2bits(float a, float b) {
    __half2 h = __floats2half2_rn(a, b);
    return *reinterpret_cast<uint32_t*>(&h);
}

// mma.sync m16n8k16 f16 -> f32 accumulate
__device__ __forceinline__ void hmma(float c[4], const uint4& a,
                                     uint32_t b0, uint32_t b1) {
    asm("mma.sync.aligned.m16n8k16.row.col.f32.f16.f16.f32 "
        "{%0,%1,%2,%3},{%4,%5,%6,%7},{%8,%9},{%0,%1,%2,%3};"
        : "+f"(c[0]), "+f"(c[1]), "+f"(c[2]), "+f"(c[3])
        : "r"(a.x), "r"(a.y), "r"(a.z), "r"(a.w), "r"(b0), "r"(b1));
}

__constant__ int c_PL[8][2] = {{1,3},{0,2},{5,7},{4,6},{0,1},{2,3},{4,5},{6,7}};

// ---------------------------------------------------------------------------
// Kernel 0: pack weights + yc table, one launch.
// gates g: 0=r, 1=z, 2=ghn, 3=gin
// ---------------------------------------------------------------------------
__device__ __forceinline__ float b4val(int g, int nl, int k,
                                       const float* Wih, const float* bih,
                                       const float* bhh) {
    if (k < 4) {
        if (g == 0) return Wih[nl * 4 + k];
        if (g == 1) return Wih[(64 + nl) * 4 + k];
        if (g == 2) return 0.0f;
        return Wih[(128 + nl) * 4 + k];
    }
    if (k == 4) {
        if (g == 0) return bih[nl] + bhh[nl];
        if (g == 1) return bih[64 + nl] + bhh[64 + nl];
        if (g == 2) return bhh[128 + nl];
        return bih[128 + nl];
    }
    return 0.0f;
}

__global__ void build_tables(const float* __restrict__ Wih, const float* __restrict__ Whh,
                             const float* __restrict__ bih, const float* __restrict__ bhh,
                             const int* __restrict__ relation,
                             const float* __restrict__ emb_const,
                             const float* __restrict__ Wcc,
                             const float* __restrict__ bcc)
{
    int i = blockIdx.x * blockDim.x + threadIdx.x;
    if (i >= 4096) {
        int j = i - 4096;
        if (j < NL * 7 * 20) {
            int o = j % 20, pq = j / 20;
            int p = pq / 7, q = pq % 7;
            const float* ce = emb_const + relation[p * 7 + q] * 4;
            float v = bcc[o];
#pragma unroll
            for (int c = 0; c < 4; c++) v = fmaf(ce[c], Wcc[o * 4 + c], v);
            g_yc[j] = fmaxf(v, 0.0f);
        }
        return;
    }
    int lane = i & 31;
    float w[4];
    char* dst;
    bool wide;

    if (i < 2048) {                       // B2: Whh r,z hi-only
        int tile = i >> 5;
        int kt = tile & 3, nt16 = tile >> 2;
        int g = nt16 >> 3, nb = nt16 & 7;
        int row = g * 64 + nb * 8 + (lane >> 2);
        int k0 = kt * 16 + 2 * (lane & 3);
        w[0] = Whh[row*64 + k0];     w[1] = Whh[row*64 + k0 + 1];
        w[2] = Whh[row*64 + k0 + 8]; w[3] = Whh[row*64 + k0 + 9];
        dst = g_Ball + SO_B2 + tile * 256 + lane * 8;  wide = false;
    } else if (i < 3072) {                // B4: Whh ghn hi/lo
        int idx = i - 2048, tile = idx >> 5;
        int kt = tile & 3, nt8 = tile >> 2;
        int row = 128 + nt8 * 8 + (lane >> 2);
        int k0 = kt * 16 + 2 * (lane & 3);
        w[0] = Whh[row*64 + k0];     w[1] = Whh[row*64 + k0 + 1];
        w[2] = Whh[row*64 + k0 + 8]; w[3] = Whh[row*64 + k0 + 9];
        dst = g_Ball + SO_B4 + tile * 512 + lane * 16; wide = true;
    } else if (i < 3584) {                // BK2: kt4 r,z hi-only
        int idx = i - 3072, tile = idx >> 5;
        int g = tile >> 3, nb = tile & 7;
        int nl = nb * 8 + (lane >> 2);
        int k0 = 2 * (lane & 3);
        w[0] = b4val(g, nl, k0,     Wih, bih, bhh);
        w[1] = b4val(g, nl, k0 + 1, Wih, bih, bhh);
        w[2] = b4val(g, nl, k0 + 8, Wih, bih, bhh);
        w[3] = b4val(g, nl, k0 + 9, Wih, bih, bhh);
        dst = g_Ball + SO_BK2 + tile * 256 + lane * 8; wide = false;
    } else {                              // BK4: kt4 ghn,gin hi/lo
        int idx = i - 3584, tile = idx >> 5;
        int g = 2 + (tile >> 3), nb = tile & 7;
        int nl = nb * 8 + (lane >> 2);
        int k0 = 2 * (lane & 3);
        w[0] = b4val(g, nl, k0,     Wih, bih, bhh);
        w[1] = b4val(g, nl, k0 + 1, Wih, bih, bhh);
        w[2] = b4val(g, nl, k0 + 8, Wih, bih, bhh);
        w[3] = b4val(g, nl, k0 + 9, Wih, bih, bhh);
        dst = g_Ball + SO_BK4 + tile * 512 + lane * 16; wide = true;
    }

    __half hi[4], lo[4];
#pragma unroll
    for (int q = 0; q < 4; q++) {
        hi[q] = __float2half_rn(w[q]);
        lo[q] = __float2half_rn(w[q] - __half2float(hi[q]));
    }
    uint2 vh;
    { __half2 p(hi[0], hi[1]); vh.x = *reinterpret_cast<uint32_t*>(&p); }
    { __half2 p(hi[2], hi[3]); vh.y = *reinterpret_cast<uint32_t*>(&p); }
    *(uint2*)dst = vh;
    if (wide) {
        uint2 vl;
        { __half2 p(lo[0], lo[1]); vl.x = *reinterpret_cast<uint32_t*>(&p); }
        { __half2 p(lo[2], lo[3]); vl.y = *reinterpret_cast<uint32_t*>(&p); }
        *(uint2*)(dst + 8) = vl;
    }
}

// ---------------------------------------------------------------------------
// Kernel 2: tensor-core GRU (identical to R7's proven mainloop).
// ---------------------------------------------------------------------------
__global__ void __launch_bounds__(GT, 2)
gru_kernel(const float* __restrict__ hist,
           const float* __restrict__ Wh,
           const float* __restrict__ bh)
{
    extern __shared__ char smem[];
    __shared__ float sW[16];   // [0..11]=Wh, [12..15]=bh
    const int tid = threadIdx.x;
    const int l   = tid & 31;
    const int wid = tid >> 5;
    const int mg  = wid >> 2;
    const int ng  = wid & 3;
    const int gtid = tid & 127;
    const int c4  = l & 3;
    const int lr  = l >> 2;
    const int seq0 = blockIdx.x * RPC;

    {
        const uint4* src = (const uint4*)g_Ball;
        uint4* dst = (uint4*)smem;
        for (int i = tid; i < 45056 / 16; i += GT) dst[i] = src[i];
        uint4 z; z.x = z.y = z.z = z.w = 0u;
        uint4* da = (uint4*)(smem + SO_A);
        for (int i = tid; i < 20480 / 16; i += GT) da[i] = z;
        if (tid < 16) sW[tid] = (tid < 12) ? Wh[tid] : bh[tid - 12];
    }
    __syncthreads();

    if (tid < RPC) {
        int seq = seq0 + tid;
        const float* hp = hist + (size_t)(seq >> 3) * (64 * 24) + (seq & 7);
        float a0v = hp[0], a1v = hp[8], a2v = hp[16];
        float xs[4];
#pragma unroll
        for (int o = 0; o < 4; o++)
            xs[o] = sigf(sW[o*3+0]*a0v + sW[o*3+1]*a1v + sW[o*3+2]*a2v + sW[12+o]);
        int mtile = tid >> 4, r = tid & 15;
        char* base = smem + SO_A + (size_t)((0 * 4 + mtile) * 5 + 4) * 512
                   + ((r & 7) * 4) * 16 + (r >> 3) * 4;
        *(uint32_t*)(base)      = h2bits(xs[0], xs[1]);
        *(uint32_t*)(base + 16) = h2bits(xs[2], xs[3]);
        *(uint32_t*)(base + 32) = h2bits(1.0f, 0.0f);
    }
    __syncthreads();

    const bool is_stager = (gtid < 32);
    const float* hbase = nullptr;
    if (is_stager) {
        int seq = seq0 + mg * 32 + gtid;
        hbase = hist + (size_t)(seq >> 3) * (64 * 24) + (seq & 7);
    }

    float hprev[2][2][2][2];   // [mt][rh][sb][jp]
#pragma unroll
    for (int a = 0; a < 2; a++)
#pragma unroll
        for (int b = 0; b < 2; b++)
#pragma unroll
            for (int c = 0; c < 2; c++) { hprev[a][b][c][0] = 0.f; hprev[a][b][c][1] = 0.f; }

#pragma unroll 1
    for (int t = 0; t < NT; t++) {
        const int buf = t & 1, bufn = buf ^ 1;
        const bool stage = is_stager && (t + 1 < NT);

        float xs[4];
        if (stage) {
            const float* hp = hbase + (size_t)(t + 1) * 24;
            float a0v = hp[0], a1v = hp[8], a2v = hp[16];
#pragma unroll
            for (int o = 0; o < 4; o++)
                xs[o] = sigf(sW[o*3+0]*a0v + sW[o*3+1]*a1v + sW[o*3+2]*a2v + sW[12+o]);
        }

        float acc[2][4][2][4];
#pragma unroll
        for (int mt = 0; mt < 2; mt++)
#pragma unroll
            for (int gt = 0; gt < 4; gt++)
#pragma unroll
                for (int sb = 0; sb < 2; sb++)
#pragma unroll
                    for (int r = 0; r < 4; r++) acc[mt][gt][sb][r] = 0.0f;

#pragma unroll
        for (int kt = 0; kt < 4; kt++) {
            uint4 a0 = *(const uint4*)(smem + SO_A + (size_t)(((buf*4) + mg*2 + 0)*5 + kt)*512 + l*16);
            uint4 a1 = *(const uint4*)(smem + SO_A + (size_t)(((buf*4) + mg*2 + 1)*5 + kt)*512 + l*16);
#pragma unroll
            for (int sb = 0; sb < 2; sb++) {
                uint4 b4 = *(const uint4*)(smem + SO_B4 + (size_t)(((ng*2+sb)*4 + kt))*512 + l*16);
                hmma(acc[0][2][sb], a0, b4.x, b4.y);
                hmma(acc[0][2][sb], a0, b4.z, b4.w);
                hmma(acc[1][2][sb], a1, b4.x, b4.y);
                hmma(acc[1][2][sb], a1, b4.z, b4.w);
#pragma unroll
                for (int gt = 0; gt < 2; gt++) {
                    uint2 b2 = *(const uint2*)(smem + SO_B2 + (size_t)(((gt*8 + ng*2+sb)*4 + kt))*256 + l*8);
                    hmma(acc[0][gt][sb], a0, b2.x, b2.y);
                    hmma(acc[1][gt][sb], a1, b2.x, b2.y);
                }
            }
        }
        {
            uint4 a0 = *(const uint4*)(smem + SO_A + (size_t)(((buf*4) + mg*2 + 0)*5 + 4)*512 + l*16);
            uint4 a1 = *(const uint4*)(smem + SO_A + (size_t)(((buf*4) + mg*2 + 1)*5 + 4)*512 + l*16);
#pragma unroll
            for (int sb = 0; sb < 2; sb++) {
#pragma unroll
                for (int gt = 0; gt < 2; gt++) {
                    uint2 b2 = *(const uint2*)(smem + SO_BK2 + (size_t)((gt*8 + ng*2+sb))*256 + l*8);
                    hmma(acc[0][gt][sb], a0, b2.x, b2.y);
                    hmma(acc[1][gt][sb], a1, b2.x, b2.y);
                }
#pragma unroll
                for (int gt = 2; gt < 4; gt++) {
                    uint4 b4 = *(const uint4*)(smem + SO_BK4 + (size_t)(((gt-2)*8 + ng*2+sb))*512 + l*16);
                    hmma(acc[0][gt][sb], a0, b4.x, b4.y);
                    hmma(acc[0][gt][sb], a0, b4.z, b4.w);
                    hmma(acc[1][gt][sb], a1, b4.x, b4.y);
                    hmma(acc[1][gt][sb], a1, b4.z, b4.w);
                }
            }
        }

#pragma unroll
        for (int mt = 0; mt < 2; mt++) {
            uint32_t hw[4];
#pragma unroll
            for (int sb = 0; sb < 2; sb++)
#pragma unroll
            for (int rh = 0; rh < 2; rh++) {
                const int rg = rh * 2;
                float r0 = siga(acc[mt][0][sb][rg]);
                float z0 = siga(acc[mt][1][sb][rg]);
                float c0 = tanha(fmaf(r0, acc[mt][2][sb][rg], acc[mt][3][sb][rg]));
                float h0 = fmaf(z0, hprev[mt][rh][sb][0] - c0, c0);
                float r1 = siga(acc[mt][0][sb][rg+1]);
                float z1 = siga(acc[mt][1][sb][rg+1]);
                float c1 = tanha(fmaf(r1, acc[mt][2][sb][rg+1], acc[mt][3][sb][rg+1]));
                float h1 = fmaf(z1, hprev[mt][rh][sb][1] - c1, c1);
                hprev[mt][rh][sb][0] = h0;
                hprev[mt][rh][sb][1] = h1;
                hw[rh + 2 * sb] = h2bits(h0, h1);

                if (t == NT - 1) {
                    const int m  = mg * 32 + mt * 16 + rh * 8 + lr;
                    const int j0 = ng * 16 + sb * 8 + 2 * c4;
                    float2 hv; hv.x = h0; hv.y = h1;
                    *(float2*)(&g_hidden[(size_t)(seq0 + m) * NH + j0]) = hv;
                }
            }
            uint4 v; v.x = hw[0]; v.y = hw[1]; v.z = hw[2]; v.w = hw[3];
            *(uint4*)(smem + SO_A + (size_t)(((bufn*4) + mg*2 + mt)*5 + ng)*512 + l*16) = v;
        }

        if (stage) {
            int m = mg * 32 + gtid;
            int mtile = m >> 4, r = m & 15;
            char* base = smem + SO_A + (size_t)((bufn * 4 + mtile) * 5 + 4) * 512
                       + ((r & 7) * 4) * 16 + (r >> 3) * 4;
            *(uint32_t*)(base)      = h2bits(xs[0], xs[1]);
            *(uint32_t*)(base + 16) = h2bits(xs[2], xs[3]);
            *(uint32_t*)(base + 32) = h2bits(1.0f, 0.0f);
        }
        asm volatile("bar.sync %0, 128;" :: "r"(1 + mg) : "memory");
    }
}

// ---------------------------------------------------------------------------
// Kernel 3: head, one WARP per batch (8 warps/block). Warp-synchronous stages,
// one block-level sync for weight staging only.
// ---------------------------------------------------------------------------
__global__ void __launch_bounds__(256)
post_kernel(const float* __restrict__ feat,
            const float* __restrict__ emb_phase,
            const float* __restrict__ Wv,  const float* __restrict__ bv,
            const float* __restrict__ Wl,  const float* __restrict__ bl,
            const float* __restrict__ Wcf, const float* __restrict__ bcf,
            const float* __restrict__ Wcm, const float* __restrict__ bcm,
            const float* __restrict__ Wfin,const float* __restrict__ bfin,
            float* __restrict__ out)
{
    __shared__ __align__(16) float sHid[8][8][64];     // [warp][lane_row][64]
    __shared__ __align__(16) float sWl[16 * 72];
    __shared__ __align__(16) float sYc[NL * 7 * 20];
    __shared__ __align__(16) float sWcf[20 * 32];
    __shared__ __align__(16) float sWcm[20 * 20];
    __shared__ __align__(16) float sMisc[96];
    __shared__ __align__(16) float sLf[8][64];         // [warp][lane*8+f]
    __shared__ __align__(16) float sLine[8][8][16];
    __shared__ __align__(16) float sPp[8][8][16];
    __shared__ __align__(16) float sVal[8][56];

    const int tid = threadIdx.x;
    const int w   = tid >> 5;
    const int l   = tid & 31;
    const int b   = blockIdx.x * 8 + w;

    for (int i = tid; i < 1152; i += 256) sWl[i] = Wl[i];
    for (int i = tid; i < 1120; i += 256) sYc[i] = g_yc[i];
    for (int i = tid; i < 640;  i += 256) sWcf[i] = Wcf[i];
    for (int i = tid; i < 400;  i += 256) sWcm[i] = Wcm[i];
    if (tid < 93) {
        float v;
        if      (tid < 4)  v = Wv[tid];
        else if (tid < 8)  v = bv[tid - 4];
        else if (tid < 24) v = bl[tid - 8];
        else if (tid < 44) v = bcf[tid - 24];
        else if (tid < 64) v = bcm[tid - 44];
        else if (tid < 84) v = Wfin[tid - 64];
        else if (tid == 84) v = bfin[0];
        else               v = emb_phase[tid - 85];
        sMisc[tid] = v;
    }

    // hid: each lane loads 16 floats of row r = l>>2
    {
        int r = l >> 2, part = l & 3;
        const float4* src = (const float4*)(&g_hidden[((size_t)b * 8 + r) * 64 + part * 16]);
        float4* dst = (float4*)(&sHid[w][r][part * 16]);
#pragma unroll
        for (int q = 0; q < 4; q++) dst[q] = src[q];
    }
    __syncthreads();   // weights + hid visible (block-wide, once)

    // lane features: idx = l and l+32
#pragma unroll
    for (int k = 0; k < 2; k++) {
        int i = l + 32 * k;
        int lane = i >> 3, f = i & 7;
        float v;
        if (f < 4) {
            float vr = feat[b * 16 + 8 + lane];
            v = sigf(fmaf(vr, sMisc[f], sMisc[4 + f]));
        } else {
            int c = f - 4;
            int pid = (int)feat[b * 16 + lane];
            v = sigf(sMisc[85 + pid * 4 + c]);
        }
        sLf[w][lane * 8 + f] = v;
    }
    __syncwarp();

    // line: 128 outputs, 4 per lane
#pragma unroll
    for (int k = 0; k < 4; k++) {
        int i = l + 32 * k;
        int lane = i >> 4, o = i & 15;
        const float* wrow = &sWl[o * 72];
        const float* lf = &sLf[w][lane * 8];
        const float* hp = &sHid[w][lane][0];
        float v = sMisc[8 + o];
#pragma unroll
        for (int c = 0; c < 8; c++)  v = fmaf(lf[c], wrow[c], v);
#pragma unroll
        for (int kk = 0; kk < 64; kk++) v = fmaf(hp[kk], wrow[8 + kk], v);
        sLine[w][lane][o] = fmaxf(v, 0.0f);
    }
    __syncwarp();

    // pp
#pragma unroll
    for (int k = 0; k < 4; k++) {
        int i = l + 32 * k;
        int p = i >> 4, o = i & 15;
        sPp[w][p][o] = sLine[w][c_PL[p][0]][o] + sLine[w][c_PL[p][1]][o];
    }
    __syncwarp();

    // pair MLP: 56 pairs in 2 rounds
#pragma unroll
    for (int rnd = 0; rnd < 2; rnd++) {
        int pr = l + 32 * rnd;
        if (pr < 56) {
            int p = pr / 7, qi = pr % 7;
            int jq = (qi < p) ? qi : qi + 1;
            const float* ppP = &sPp[w][p][0];
            const float* ppJ = &sPp[w][jq][0];
            float xf[20];
#pragma unroll
            for (int o = 0; o < 20; o++) {
                const float* wc = &sWcf[o * 32];
                float v = sMisc[24 + o];
#pragma unroll
                for (int c = 0; c < 16; c++) v = fmaf(ppP[c], wc[c],      v);
#pragma unroll
                for (int c = 0; c < 16; c++) v = fmaf(ppJ[c], wc[16 + c], v);
                xf[o] = fmaxf(v, 0.0f) * sYc[(p * 7 + qi) * 20 + o];
            }
            float val = sMisc[84];
#pragma unroll
            for (int o = 0; o < 20; o++) {
                const float* wm = &sWcm[o * 20];
                float v = sMisc[44 + o];
#pragma unroll
                for (int c = 0; c < 20; c++) v = fmaf(xf[c], wm[c], v);
                val = fmaf(fmaxf(v, 0.0f), sMisc[64 + o], val);
            }
            sVal[w][pr] = val;
        }
    }
    __syncwarp();

    if (l < NL) {
        float acc = 0.0f;
#pragma unroll
        for (int q = 0; q < 7; q++) acc += sVal[w][l * 7 + q];
        out[b * 8 + l] = acc;
    }
}

// ---------------------------------------------------------------------------
// Launch
// ---------------------------------------------------------------------------
extern "C" void kernel_launch(void* const* d_in, const int* in_sizes, int n_in,
                              void* d_out, int out_size)
{
    const float* feature  = (const float*)d_in[0];
    const float* history  = (const float*)d_in[1];
    const int*   relation = (const int*)  d_in[2];
    const float* emb_phase= (const float*)d_in[3];
    const float* Wv       = (const float*)d_in[4];
    const float* bv       = (const float*)d_in[5];
    const float* Wh       = (const float*)d_in[6];
    const float* bh       = (const float*)d_in[7];
    const float* Wih      = (const float*)d_in[8];
    const float* Whh      = (const float*)d_in[9];
    const float* bih      = (const float*)d_in[10];
    const float* bhh      = (const float*)d_in[11];
    const float* Wl       = (const float*)d_in[12];
    const float* bl       = (const float*)d_in[13];
    const float* emb_const= (const float*)d_in[14];
    const float* Wcf      = (const float*)d_in[15];
    const float* bcf      = (const float*)d_in[16];
    const float* Wcc      = (const float*)d_in[17];
    const float* bcc      = (const float*)d_in[18];
    const float* Wcm      = (const float*)d_in[19];
    const float* bcm      = (const float*)d_in[20];
    const float* Wfin     = (const float*)d_in[21];
    const float* bfin     = (const float*)d_in[22];
    float* out = (float*)d_out;

    cudaFuncSetAttribute(gru_kernel, cudaFuncAttributeMaxDynamicSharedMemorySize, SMEMSZ);

    build_tables<<<21, 256>>>(Wih, Whh, bih, bhh, relation, emb_const, Wcc, bcc);
    gru_kernel<<<GCTA, GT, SMEMSZ>>>(history, Wh, bh);
    post_kernel<<<NB / 8, 256>>>(feature, emb_phase, Wv, bv, Wl, bl,
                                 Wcf, bcf, Wcm, bcm, Wfin, bfin, out);
}

// round 12
// speedup vs baseline: 1.6260x; 1.6260x over previous
#include <cuda_runtime.h>
#include <cuda_fp16.h>
#include <stdint.h>
#include <math.h>

#define NB   2048
#define NT   64
#define NL   8
#define NH   64
#define NSEQ (NB*NL)          // 16384
#define RPC  64               // rows per GRU CTA
#define GCTA (NSEQ/RPC)       // 256 CTAs
#define GT   256              // GRU threads per CTA

// ---- SMEM map for GRU mainloop (bytes) -------------------------------------
#define SO_B2   0
#define SO_B4   16384
#define SO_BK2  32768
#define SO_BK4  36864
#define SO_A    45056
#define SMEMSZ  65536

// ---- scratch (__device__ globals; allocs forbidden) -----------------------
__device__ __align__(16) float g_hidden[NSEQ * NH];   // [seq][64]
__device__ __align__(16) char g_Ball[45056];          // packed B regions
__device__ __align__(16) float g_yc[NL * 7 * 20];     // relu(ce@Wcc^T+bcc)

__device__ __forceinline__ float sigf(float x) {
    return __fdividef(1.0f, 1.0f + __expf(-x));
}
__device__ __forceinline__ float tanha(float x) {
    float y;
    asm("tanh.approx.f32 %0, %1;" : "=f"(y) : "f"(x));
    return y;
}
__device__ __forceinline__ float siga(float x) {     // sigmoid via tanh, 1 MUFU
    return fmaf(0.5f, tanha(0.5f * x), 0.5f);
}
__device__ __forceinline__ uint32_t h2bits(float a, float b) {
    __half2 h = __floats2half2_rn(a, b);
    return *reinterpret_cast<uint32_t*>(&h);
}

// mma.sync m16n8k16 f16 -> f32 accumulate
__device__ __forceinline__ void hmma(float c[4], const uint4& a,
                                     uint32_t b0, uint32_t b1) {
    asm("mma.sync.aligned.m16n8k16.row.col.f32.f16.f16.f32 "
        "{%0,%1,%2,%3},{%4,%5,%6,%7},{%8,%9},{%0,%1,%2,%3};"
        : "+f"(c[0]), "+f"(c[1]), "+f"(c[2]), "+f"(c[3])
        : "r"(a.x), "r"(a.y), "r"(a.z), "r"(a.w), "r"(b0), "r"(b1));
}

__constant__ int c_PL[8][2] = {{1,3},{0,2},{5,7},{4,6},{0,1},{2,3},{4,5},{6,7}};

// ---------------------------------------------------------------------------
// Kernel 0: pack weights + yc table, one launch.
// gates g: 0=r, 1=z, 2=ghn, 3=gin
// ---------------------------------------------------------------------------
__device__ __forceinline__ float b4val(int g, int nl, int k,
                                       const float* Wih, const float* bih,
                                       const float* bhh) {
    if (k < 4) {
        if (g == 0) return Wih[nl * 4 + k];
        if (g == 1) return Wih[(64 + nl) * 4 + k];
        if (g == 2) return 0.0f;
        return Wih[(128 + nl) * 4 + k];
    }
    if (k == 4) {
        if (g == 0) return bih[nl] + bhh[nl];
        if (g == 1) return bih[64 + nl] + bhh[64 + nl];
        if (g == 2) return bhh[128 + nl];
        return bih[128 + nl];
    }
    return 0.0f;
}

__global__ void build_tables(const float* __restrict__ Wih, const float* __restrict__ Whh,
                             const float* __restrict__ bih, const float* __restrict__ bhh,
                             const int* __restrict__ relation,
                             const float* __restrict__ emb_const,
                             const float* __restrict__ Wcc,
                             const float* __restrict__ bcc)
{
    int i = blockIdx.x * blockDim.x + threadIdx.x;
    if (i >= 4096) {
        int j = i - 4096;
        if (j < NL * 7 * 20) {
            int o = j % 20, pq = j / 20;
            int p = pq / 7, q = pq % 7;
            const float* ce = emb_const + relation[p * 7 + q] * 4;
            float v = bcc[o];
#pragma unroll
            for (int c = 0; c < 4; c++) v = fmaf(ce[c], Wcc[o * 4 + c], v);
            g_yc[j] = fmaxf(v, 0.0f);
        }
        return;
    }
    int lane = i & 31;
    float w[4];
    char* dst;
    bool wide;

    if (i < 2048) {                       // B2: Whh r,z hi-only
        int tile = i >> 5;
        int kt = tile & 3, nt16 = tile >> 2;
        int g = nt16 >> 3, nb = nt16 & 7;
        int row = g * 64 + nb * 8 + (lane >> 2);
        int k0 = kt * 16 + 2 * (lane & 3);
        w[0] = Whh[row*64 + k0];     w[1] = Whh[row*64 + k0 + 1];
        w[2] = Whh[row*64 + k0 + 8]; w[3] = Whh[row*64 + k0 + 9];
        dst = g_Ball + SO_B2 + tile * 256 + lane * 8;  wide = false;
    } else if (i < 3072) {                // B4: Whh ghn hi/lo
        int idx = i - 2048, tile = idx >> 5;
        int kt = tile & 3, nt8 = tile >> 2;
        int row = 128 + nt8 * 8 + (lane >> 2);
        int k0 = kt * 16 + 2 * (lane & 3);
        w[0] = Whh[row*64 + k0];     w[1] = Whh[row*64 + k0 + 1];
        w[2] = Whh[row*64 + k0 + 8]; w[3] = Whh[row*64 + k0 + 9];
        dst = g_Ball + SO_B4 + tile * 512 + lane * 16; wide = true;
    } else if (i < 3584) {                // BK2: kt4 r,z hi-only
        int idx = i - 3072, tile = idx >> 5;
        int g = tile >> 3, nb = tile & 7;
        int nl = nb * 8 + (lane >> 2);
        int k0 = 2 * (lane & 3);
        w[0] = b4val(g, nl, k0,     Wih, bih, bhh);
        w[1] = b4val(g, nl, k0 + 1, Wih, bih, bhh);
        w[2] = b4val(g, nl, k0 + 8, Wih, bih, bhh);
        w[3] = b4val(g, nl, k0 + 9, Wih, bih, bhh);
        dst = g_Ball + SO_BK2 + tile * 256 + lane * 8; wide = false;
    } else {                              // BK4: kt4 ghn,gin hi/lo
        int idx = i - 3584, tile = idx >> 5;
        int g = 2 + (tile >> 3), nb = tile & 7;
        int nl = nb * 8 + (lane >> 2);
        int k0 = 2 * (lane & 3);
        w[0] = b4val(g, nl, k0,     Wih, bih, bhh);
        w[1] = b4val(g, nl, k0 + 1, Wih, bih, bhh);
        w[2] = b4val(g, nl, k0 + 8, Wih, bih, bhh);
        w[3] = b4val(g, nl, k0 + 9, Wih, bih, bhh);
        dst = g_Ball + SO_BK4 + tile * 512 + lane * 16; wide = true;
    }

    __half hi[4], lo[4];
#pragma unroll
    for (int q = 0; q < 4; q++) {
        hi[q] = __float2half_rn(w[q]);
        lo[q] = __float2half_rn(w[q] - __half2float(hi[q]));
    }
    uint2 vh;
    { __half2 p(hi[0], hi[1]); vh.x = *reinterpret_cast<uint32_t*>(&p); }
    { __half2 p(hi[2], hi[3]); vh.y = *reinterpret_cast<uint32_t*>(&p); }
    *(uint2*)dst = vh;
    if (wide) {
        uint2 vl;
        { __half2 p(lo[0], lo[1]); vl.x = *reinterpret_cast<uint32_t*>(&p); }
        { __half2 p(lo[2], lo[3]); vl.y = *reinterpret_cast<uint32_t*>(&p); }
        *(uint2*)(dst + 8) = vl;
    }
}

// ---------------------------------------------------------------------------
// Kernel 2: tensor-core GRU (R7's proven mainloop).
// ---------------------------------------------------------------------------
__global__ void __launch_bounds__(GT, 2)
gru_kernel(const float* __restrict__ hist,
           const float* __restrict__ Wh,
           const float* __restrict__ bh)
{
    extern __shared__ char smem[];
    __shared__ float sW[16];   // [0..11]=Wh, [12..15]=bh
    const int tid = threadIdx.x;
    const int l   = tid & 31;
    const int wid = tid >> 5;
    const int mg  = wid >> 2;
    const int ng  = wid & 3;
    const int gtid = tid & 127;
    const int c4  = l & 3;
    const int lr  = l >> 2;
    const int seq0 = blockIdx.x * RPC;

    {
        const uint4* src = (const uint4*)g_Ball;
        uint4* dst = (uint4*)smem;
        for (int i = tid; i < 45056 / 16; i += GT) dst[i] = src[i];
        uint4 z; z.x = z.y = z.z = z.w = 0u;
        uint4* da = (uint4*)(smem + SO_A);
        for (int i = tid; i < 20480 / 16; i += GT) da[i] = z;
        if (tid < 16) sW[tid] = (tid < 12) ? Wh[tid] : bh[tid - 12];
    }
    __syncthreads();

    if (tid < RPC) {
        int seq = seq0 + tid;
        const float* hp = hist + (size_t)(seq >> 3) * (64 * 24) + (seq & 7);
        float a0v = hp[0], a1v = hp[8], a2v = hp[16];
        float xs[4];
#pragma unroll
        for (int o = 0; o < 4; o++)
            xs[o] = sigf(sW[o*3+0]*a0v + sW[o*3+1]*a1v + sW[o*3+2]*a2v + sW[12+o]);
        int mtile = tid >> 4, r = tid & 15;
        char* base = smem + SO_A + (size_t)((0 * 4 + mtile) * 5 + 4) * 512
                   + ((r & 7) * 4) * 16 + (r >> 3) * 4;
        *(uint32_t*)(base)      = h2bits(xs[0], xs[1]);
        *(uint32_t*)(base + 16) = h2bits(xs[2], xs[3]);
        *(uint32_t*)(base + 32) = h2bits(1.0f, 0.0f);
    }
    __syncthreads();

    const bool is_stager = (gtid < 32);
    const float* hbase = nullptr;
    if (is_stager) {
        int seq = seq0 + mg * 32 + gtid;
        hbase = hist + (size_t)(seq >> 3) * (64 * 24) + (seq & 7);
    }

    float hprev[2][2][2][2];   // [mt][rh][sb][jp]
#pragma unroll
    for (int a = 0; a < 2; a++)
#pragma unroll
        for (int b = 0; b < 2; b++)
#pragma unroll
            for (int c = 0; c < 2; c++) { hprev[a][b][c][0] = 0.f; hprev[a][b][c][1] = 0.f; }

#pragma unroll 1
    for (int t = 0; t < NT; t++) {
        const int buf = t & 1, bufn = buf ^ 1;
        const bool stage = is_stager && (t + 1 < NT);

        float xs[4];
        if (stage) {
            const float* hp = hbase + (size_t)(t + 1) * 24;
            float a0v = hp[0], a1v = hp[8], a2v = hp[16];
#pragma unroll
            for (int o = 0; o < 4; o++)
                xs[o] = sigf(sW[o*3+0]*a0v + sW[o*3+1]*a1v + sW[o*3+2]*a2v + sW[12+o]);
        }

        float acc[2][4][2][4];
#pragma unroll
        for (int mt = 0; mt < 2; mt++)
#pragma unroll
            for (int gt = 0; gt < 4; gt++)
#pragma unroll
                for (int sb = 0; sb < 2; sb++)
#pragma unroll
                    for (int r = 0; r < 4; r++) acc[mt][gt][sb][r] = 0.0f;

#pragma unroll
        for (int kt = 0; kt < 4; kt++) {
            uint4 a0 = *(const uint4*)(smem + SO_A + (size_t)(((buf*4) + mg*2 + 0)*5 + kt)*512 + l*16);
            uint4 a1 = *(const uint4*)(smem + SO_A + (size_t)(((buf*4) + mg*2 + 1)*5 + kt)*512 + l*16);
#pragma unroll
            for (int sb = 0; sb < 2; sb++) {
                uint4 b4 = *(const uint4*)(smem + SO_B4 + (size_t)(((ng*2+sb)*4 + kt))*512 + l*16);
                hmma(acc[0][2][sb], a0, b4.x, b4.y);
                hmma(acc[0][2][sb], a0, b4.z, b4.w);
                hmma(acc[1][2][sb], a1, b4.x, b4.y);
                hmma(acc[1][2][sb], a1, b4.z, b4.w);
#pragma unroll
                for (int gt = 0; gt < 2; gt++) {
                    uint2 b2 = *(const uint2*)(smem + SO_B2 + (size_t)(((gt*8 + ng*2+sb)*4 + kt))*256 + l*8);
                    hmma(acc[0][gt][sb], a0, b2.x, b2.y);
                    hmma(acc[1][gt][sb], a1, b2.x, b2.y);
                }
            }
        }
        {
            uint4 a0 = *(const uint4*)(smem + SO_A + (size_t)(((buf*4) + mg*2 + 0)*5 + 4)*512 + l*16);
            uint4 a1 = *(const uint4*)(smem + SO_A + (size_t)(((buf*4) + mg*2 + 1)*5 + 4)*512 + l*16);
#pragma unroll
            for (int sb = 0; sb < 2; sb++) {
#pragma unroll
                for (int gt = 0; gt < 2; gt++) {
                    uint2 b2 = *(const uint2*)(smem + SO_BK2 + (size_t)((gt*8 + ng*2+sb))*256 + l*8);
                    hmma(acc[0][gt][sb], a0, b2.x, b2.y);
                    hmma(acc[1][gt][sb], a1, b2.x, b2.y);
                }
#pragma unroll
                for (int gt = 2; gt < 4; gt++) {
                    uint4 b4 = *(const uint4*)(smem + SO_BK4 + (size_t)(((gt-2)*8 + ng*2+sb))*512 + l*16);
                    hmma(acc[0][gt][sb], a0, b4.x, b4.y);
                    hmma(acc[0][gt][sb], a0, b4.z, b4.w);
                    hmma(acc[1][gt][sb], a1, b4.x, b4.y);
                    hmma(acc[1][gt][sb], a1, b4.z, b4.w);
                }
            }
        }

#pragma unroll
        for (int mt = 0; mt < 2; mt++) {
            uint32_t hw[4];
#pragma unroll
            for (int sb = 0; sb < 2; sb++)
#pragma unroll
            for (int rh = 0; rh < 2; rh++) {
                const int rg = rh * 2;
                float r0 = siga(acc[mt][0][sb][rg]);
                float z0 = siga(acc[mt][1][sb][rg]);
                float c0 = tanha(fmaf(r0, acc[mt][2][sb][rg], acc[mt][3][sb][rg]));
                float h0 = fmaf(z0, hprev[mt][rh][sb][0] - c0, c0);
                float r1 = siga(acc[mt][0][sb][rg+1]);
                float z1 = siga(acc[mt][1][sb][rg+1]);
                float c1 = tanha(fmaf(r1, acc[mt][2][sb][rg+1], acc[mt][3][sb][rg+1]));
                float h1 = fmaf(z1, hprev[mt][rh][sb][1] - c1, c1);
                hprev[mt][rh][sb][0] = h0;
                hprev[mt][rh][sb][1] = h1;
                hw[rh + 2 * sb] = h2bits(h0, h1);

                if (t == NT - 1) {
                    const int m  = mg * 32 + mt * 16 + rh * 8 + lr;
                    const int j0 = ng * 16 + sb * 8 + 2 * c4;
                    float2 hv; hv.x = h0; hv.y = h1;
                    *(float2*)(&g_hidden[(size_t)(seq0 + m) * NH + j0]) = hv;
                }
            }
            uint4 v; v.x = hw[0]; v.y = hw[1]; v.z = hw[2]; v.w = hw[3];
            *(uint4*)(smem + SO_A + (size_t)(((bufn*4) + mg*2 + mt)*5 + ng)*512 + l*16) = v;
        }

        if (stage) {
            int m = mg * 32 + gtid;
            int mtile = m >> 4, r = m & 15;
            char* base = smem + SO_A + (size_t)((bufn * 4 + mtile) * 5 + 4) * 512
                       + ((r & 7) * 4) * 16 + (r >> 3) * 4;
            *(uint32_t*)(base)      = h2bits(xs[0], xs[1]);
            *(uint32_t*)(base + 16) = h2bits(xs[2], xs[3]);
            *(uint32_t*)(base + 32) = h2bits(1.0f, 0.0f);
        }
        asm volatile("bar.sync %0, 128;" :: "r"(1 + mg) : "memory");
    }
}

// ---------------------------------------------------------------------------
// Kernel 3: lane MLP + phase competition head. 4 batches per 256-thread block.
// (R7's proven version, 40.7us)
// ---------------------------------------------------------------------------
__global__ void __launch_bounds__(256)
post_kernel(const float* __restrict__ feat,
            const float* __restrict__ emb_phase,
            const float* __restrict__ Wv,  const float* __restrict__ bv,
            const float* __restrict__ Wl,  const float* __restrict__ bl,
            const float* __restrict__ Wcf, const float* __restrict__ bcf,
            const float* __restrict__ Wcm, const float* __restrict__ bcm,
            const float* __restrict__ Wfin,const float* __restrict__ bfin,
            float* __restrict__ out)
{
    __shared__ float s_hid[4][NL][NH];
    __shared__ float s_lf[4][NL][8];
    __shared__ float s_line[4][NL][16];
    __shared__ float s_pp[4][NL][16];
    __shared__ float s_Wl[16 * 72];
    __shared__ float s_yc[NL * 7 * 20];
    __shared__ float s_val[4][NL][7];

    const int tid = threadIdx.x;
    const int sub = tid >> 6;          // 0..3
    const int st  = tid & 63;
    const int b   = blockIdx.x * 4 + sub;

    for (int i = tid; i < 16 * 72; i += 256) s_Wl[i] = Wl[i];
    for (int i = tid; i < NL * 7 * 20; i += 256) s_yc[i] = g_yc[i];
    for (int i = st; i < NL * NH; i += 64)
        s_hid[sub][i >> 6][i & 63] = g_hidden[(size_t)b * (NL * NH) + i];

    {
        int l = st >> 3, f = st & 7;
        if (f < 4) {
            float vr = feat[b * 16 + 8 + l];
            s_lf[sub][l][f] = sigf(fmaf(vr, Wv[f], bv[f]));
        } else {
            int c = f - 4;
            int pid = (int)feat[b * 16 + l];
            s_lf[sub][l][f] = sigf(emb_phase[pid * 4 + c]);
        }
    }
    __syncthreads();

    for (int i = st; i < NL * 16; i += 64) {
        int l = i >> 4, o = i & 15;
        const float* wrow = &s_Wl[o * 72];
        float v = bl[o];
#pragma unroll
        for (int c = 0; c < 8; c++)  v = fmaf(s_lf[sub][l][c], wrow[c], v);
#pragma unroll
        for (int k = 0; k < NH; k++) v = fmaf(s_hid[sub][l][k], wrow[8 + k], v);
        s_line[sub][l][o] = fmaxf(v, 0.0f);
    }
    __syncthreads();

    for (int i = st; i < NL * 16; i += 64) {
        int p = i >> 4, o = i & 15;
        s_pp[sub][p][o] = s_line[sub][c_PL[p][0]][o] + s_line[sub][c_PL[p][1]][o];
    }
    __syncthreads();

    if (st < 56) {
        int p = st / 7, qi = st % 7;
        int jq = (qi < p) ? qi : qi + 1;

        float xf[20];
#pragma unroll
        for (int o = 0; o < 20; o++) {
            const float* wc = Wcf + o * 32;
            float v = bcf[o];
#pragma unroll
            for (int c = 0; c < 16; c++) v = fmaf(s_pp[sub][p][c],  wc[c],      v);
#pragma unroll
            for (int c = 0; c < 16; c++) v = fmaf(s_pp[sub][jq][c], wc[16 + c], v);
            xf[o] = fmaxf(v, 0.0f) * s_yc[(p * 7 + qi) * 20 + o];
        }
        float val = bfin[0];
#pragma unroll
        for (int o = 0; o < 20; o++) {
            const float* wm = Wcm + o * 20;
            float v = bcm[o];
#pragma unroll
            for (int c = 0; c < 20; c++) v = fmaf(xf[c], wm[c], v);
            val = fmaf(fmaxf(v, 0.0f), Wfin[o], val);
        }
        s_val[sub][p][qi] = val;
    }
    __syncthreads();

    if (st < NL) {
        float acc = 0.0f;
#pragma unroll
        for (int q = 0; q < 7; q++) acc += s_val[sub][st][q];
        out[b * NL + st] = acc;
    }
}

// ---------------------------------------------------------------------------
// Launch
// ---------------------------------------------------------------------------
extern "C" void kernel_launch(void* const* d_in, const int* in_sizes, int n_in,
                              void* d_out, int out_size)
{
    const float* feature  = (const float*)d_in[0];
    const float* history  = (const float*)d_in[1];
    const int*   relation = (const int*)  d_in[2];
    const float* emb_phase= (const float*)d_in[3];
    const float* Wv       = (const float*)d_in[4];
    const float* bv       = (const float*)d_in[5];
    const float* Wh       = (const float*)d_in[6];
    const float* bh       = (const float*)d_in[7];
    const float* Wih      = (const float*)d_in[8];
    const float* Whh      = (const float*)d_in[9];
    const float* bih      = (const float*)d_in[10];
    const float* bhh      = (const float*)d_in[11];
    const float* Wl       = (const float*)d_in[12];
    const float* bl       = (const float*)d_in[13];
    const float* emb_const= (const float*)d_in[14];
    const float* Wcf      = (const float*)d_in[15];
    const float* bcf      = (const float*)d_in[16];
    const float* Wcc      = (const float*)d_in[17];
    const float* bcc      = (const float*)d_in[18];
    const float* Wcm      = (const float*)d_in[19];
    const float* bcm      = (const float*)d_in[20];
    const float* Wfin     = (const float*)d_in[21];
    const float* bfin     = (const float*)d_in[22];
    float* out = (float*)d_out;

    cudaFuncSetAttribute(gru_kernel, cudaFuncAttributeMaxDynamicSharedMemorySize, SMEMSZ);

    build_tables<<<21, 256>>>(Wih, Whh, bih, bhh, relation, emb_const, Wcc, bcc);
    gru_kernel<<<GCTA, GT, SMEMSZ>>>(history, Wh, bh);
    post_kernel<<<NB / 4, 256>>>(feature, emb_phase, Wv, bv, Wl, bl,
                                 Wcf, bcf, Wcm, bcm, Wfin, bfin, out);
}